// round 16
// baseline (speedup 1.0000x reference)
#include <cuda_runtime.h>
#include <cuda_fp16.h>
#include <cstdint>

// ---------------------------------------------------------------------------
// out[b,h,w,s,co] = ELU( conv3x3_SAME(x, W_s) ),  W_s = mu + n_s*exp(logstd)
// GEMM: C[65536,1024] = A_im2col[65536,576] * W[576,1024]; C row-major == out.
// fp16 m16n8k16 HMMA. A: CTA-resident smem halo patch + LDSM. B: weights
// pre-packed in MMA FRAGMENT ORDER (N-permuted for a coalesced epilogue).
// R15: prefetch.global.L1 of tap+1's B fragments (2 lanes/warp) to cover the
// ~240-cyc L2-hit latency that was idling the tensor pipe at a fixed 68%.
// ---------------------------------------------------------------------------
#define NS    8
#define CINV  64
#define COUTV 128
#define NTOTV 1024
#define NTAP  9
#define PSTR  72
#define PATCH_HALFS (264 * PSTR)            // 4 h-rows x 66 w
#define SMEM_TOTAL (PATCH_HALFS * 2)        // 38016 B
#define WF_TAP (128 * 4 * 32)               // uint2 elems per tap in g_Wf

__device__ __half g_Xh[16 * 64 * 64 * CINV];
// B in fragment order: [tap][n8=0..127][kk=0..3][lane=0..31] -> uint2 {b0,b1}
__device__ uint2 g_Wf[NTAP * WF_TAP];

// ============================ helpers ======================================
__device__ __forceinline__ void cp_async16(uint32_t dst, const void* src) {
    asm volatile("cp.async.cg.shared.global [%0], [%1], 16;" :: "r"(dst), "l"(src));
}
__device__ __forceinline__ void cp_commit() { asm volatile("cp.async.commit_group;"); }
template <int N> __device__ __forceinline__ void cp_wait() {
    asm volatile("cp.async.wait_group %0;" :: "n"(N));
}
__device__ __forceinline__ uint32_t smem_u32(const void* p) {
    uint32_t a;
    asm("{ .reg .u64 t; cvta.to.shared.u64 t, %1; cvt.u32.u64 %0, t; }" : "=r"(a) : "l"(p));
    return a;
}
__device__ __forceinline__ void ldsm4(uint32_t& r0, uint32_t& r1, uint32_t& r2,
                                      uint32_t& r3, uint32_t addr) {
    asm volatile("ldmatrix.sync.aligned.m8n8.x4.shared.b16 {%0,%1,%2,%3}, [%4];"
                 : "=r"(r0), "=r"(r1), "=r"(r2), "=r"(r3) : "r"(addr));
}
__device__ __forceinline__ void mma_f16(float* c, const uint32_t* a, uint2 b) {
    asm volatile(
        "mma.sync.aligned.m16n8k16.row.col.f32.f16.f16.f32 "
        "{%0,%1,%2,%3}, {%4,%5,%6,%7}, {%8,%9}, {%0,%1,%2,%3};"
        : "+f"(c[0]), "+f"(c[1]), "+f"(c[2]), "+f"(c[3])
        : "r"(a[0]), "r"(a[1]), "r"(a[2]), "r"(a[3]), "r"(b.x), "r"(b.y));
}
__device__ __forceinline__ float elu1(float v) {
    return v > 0.f ? v : (__expf(v) - 1.0f);
}

struct Frags { uint32_t a[4][4]; uint2 b[4]; };

// ============================ fused prep kernel ============================
__global__ void prep(const float* __restrict__ x,
                     const float* __restrict__ mu,
                     const float* __restrict__ logstd,
                     const float* __restrict__ noise) {
    int idx = blockIdx.x * blockDim.x + threadIdx.x;      // 1048576 threads
    float4 v = reinterpret_cast<const float4*>(x)[idx];
    __half2* xo = reinterpret_cast<__half2*>(g_Xh) + idx * 2;
    xo[0] = __floats2half2_rn(v.x, v.y);
    xo[1] = __floats2half2_rn(v.z, v.w);

    if (idx < NTAP * WF_TAP) {                            // 147456
        int lane = idx & 31;
        int kk   = (idx >> 5) & 3;
        int n8   = (idx >> 7) & 127;
        int tap  = idx >> 14;
        // N-permutation: (n8 = group*4 + nf, nj = lane>>2) -> column
        // group*32 + (nj>>1)*8 + nf*2 + (nj&1): lane epilogue values land on
        // 8 contiguous columns.
        int nf   = n8 & 3;
        int nj   = lane >> 2;
        int n    = ((n8 >> 2) << 5) + ((nj >> 1) << 3) + (nf << 1) + (nj & 1);
        int s  = n >> 7, co = n & 127;
        int k0 = (kk << 4) + ((lane & 3) << 1);
        float w[4];
        #pragma unroll
        for (int j = 0; j < 4; j++) {
            int ci = k0 + (j >> 1) * 8 + (j & 1);
            int mi = (tap * CINV + ci) * COUTV + co;
            int ni = ((s * NTAP + tap) * CINV + ci) * COUTV + co;
            w[j] = mu[mi] + noise[ni] * expf(logstd[mi]);
        }
        uint2 r;
        __half2 h0 = __floats2half2_rn(w[0], w[1]);
        __half2 h1 = __floats2half2_rn(w[2], w[3]);
        r.x = *reinterpret_cast<uint32_t*>(&h0);
        r.y = *reinterpret_cast<uint32_t*>(&h1);
        g_Wf[idx] = r;
    }
}

// ============================ conv kernel ==================================
__device__ __forceinline__ void load_B_frags(Frags& F, int tap, int kk,
                                             const uint2* wf) {
    #pragma unroll
    for (int nf = 0; nf < 4; nf++)
        F.b[nf] = __ldg(wf + tap * WF_TAP + nf * 128 + kk * 32);
}
// 2 lanes cover the warp's full 256B B slice (2 lines) per nf
__device__ __forceinline__ void prefetch_B(int tap, int kk, const uint2* wf, int lid) {
    if ((lid & 15) == 0) {
        #pragma unroll
        for (int nf = 0; nf < 4; nf++)
            asm volatile("prefetch.global.L1 [%0];"
                         :: "l"(wf + tap * WF_TAP + nf * 128 + kk * 32));
    }
}
__device__ __forceinline__ void load_A_frags(Frags& F, int tap, int kk,
                                             uint32_t pA0) {
    const int dy = tap / 3 - 1, dx = tap % 3 - 1;
    const uint32_t aBase = pA0 + (uint32_t)((dy * 66 + dx) * PSTR * 2 + kk * 32);
    #pragma unroll
    for (int mf = 0; mf < 4; mf++)
        ldsm4(F.a[mf][0], F.a[mf][1], F.a[mf][2], F.a[mf][3],
              aBase + (uint32_t)(mf * 16 * PSTR * 2));
}
__device__ __forceinline__ void load_frags(Frags& F, int tap, int kk,
                                           uint32_t pA0, const uint2* wf) {
    load_B_frags(F, tap, kk, wf);
    load_A_frags(F, tap, kk, pA0);
}

__global__ __launch_bounds__(256, 2)
void conv_mma_kernel(float* __restrict__ out) {
    extern __shared__ __half smem[];
    const uint32_t patch_u32 = smem_u32(smem);

    const int tid = threadIdx.x, wid = tid >> 5, lid = tid & 31;
    const int mtile = blockIdx.x, ntile = blockIdx.y;
    const int b  = mtile >> 5;
    const int h0 = (mtile & 31) << 1;
    const int wm = wid & 1, wn = wid >> 1;     // warp tile 64m x 32n

    const uint32_t a_lane = (uint32_t)((lid & 15) * PSTR + (lid >> 4) * 8) * 2u;
    const uint32_t pA0    = patch_u32 + (uint32_t)(((wm + 1) * 66 + 1) * PSTR * 2) + a_lane;
    const uint2* wf = g_Wf + ((size_t)(ntile * 16 + wn * 4) << 7) + lid;

    // ---- prologue: load halo patch (cp.async) ----
    #pragma unroll
    for (int i = 0; i < 9; i++) {              // 2112 chunks / 256 threads
        int lin = tid + (i << 8);
        if (lin >= 2112) break;
        int row = lin >> 3, c = lin & 7;
        int hh = row / 66, ww = row % 66;
        int h = h0 - 1 + hh, w = ww - 1;
        uint32_t dst = patch_u32 + (uint32_t)(row * PSTR + (c << 3)) * 2u;
        if ((unsigned)h < 64u && (unsigned)w < 64u) {
            cp_async16(dst, g_Xh + (size_t)(((b << 6) + h) * 64 + w) * CINV + (c << 3));
        } else {
            asm volatile("st.shared.v4.b32 [%0], {%1,%1,%1,%1};" :: "r"(dst), "r"(0u) : "memory");
        }
    }
    cp_commit();

    float acc[4][4][4];
    #pragma unroll
    for (int i = 0; i < 4; i++)
        #pragma unroll
        for (int j = 0; j < 4; j++)
            #pragma unroll
            for (int k = 0; k < 4; k++) acc[i][j][k] = 0.f;

    Frags f[2];
    load_B_frags(f[0], 0, 0, wf);   // independent of the patch
    // warm L1 for the rest of tap0 and tap1 while cp.async drains
    #pragma unroll
    for (int kk = 1; kk < 4; kk++) prefetch_B(0, kk, wf, lid);
    #pragma unroll
    for (int kk = 0; kk < 4; kk++) prefetch_B(1, kk, wf, lid);

    cp_wait<0>();
    __syncthreads();                // the only barrier

    load_A_frags(f[0], 0, 0, pA0);

    #pragma unroll                  // full unroll: tap/kk immediate everywhere
    for (int tap = 0; tap < NTAP; tap++) {
        #pragma unroll
        for (int kk = 0; kk < 4; kk++) {
            Frags& cur = f[kk & 1];
            Frags& nxt = f[(kk & 1) ^ 1];
            if (kk < 3)        load_frags(nxt, tap, kk + 1, pA0, wf);
            else if (tap < 8)  load_frags(nxt, tap + 1, 0, pA0, wf);
            if (tap < 8)       prefetch_B(tap + 1, kk, wf, lid);   // ~4-step lead
            #pragma unroll
            for (int mf = 0; mf < 4; mf++)
                #pragma unroll
                for (int nf = 0; nf < 4; nf++)
                    mma_f16(acc[mf][nf], cur.a[mf], cur.b[nf]);
        }
    }

    // ---- epilogue: fast ELU + coalesced float4 stores ----
    const int l4 = lid >> 2, lm = lid & 3;
    const int colb = (ntile << 7) + (wn << 5) + (lm << 3);
    #pragma unroll
    for (int mf = 0; mf < 4; mf++) {
        int row = (mtile << 7) + wm * 64 + mf * 16 + l4;
        float* o0 = out + (size_t)row * NTOTV + colb;      // row l4
        float* o1 = o0 + 8 * NTOTV;                        // row l4+8
        float4 q0, q1, r0, r1;
        q0.x = elu1(acc[mf][0][0]); q0.y = elu1(acc[mf][0][1]);
        q0.z = elu1(acc[mf][1][0]); q0.w = elu1(acc[mf][1][1]);
        q1.x = elu1(acc[mf][2][0]); q1.y = elu1(acc[mf][2][1]);
        q1.z = elu1(acc[mf][3][0]); q1.w = elu1(acc[mf][3][1]);
        r0.x = elu1(acc[mf][0][2]); r0.y = elu1(acc[mf][0][3]);
        r0.z = elu1(acc[mf][1][2]); r0.w = elu1(acc[mf][1][3]);
        r1.x = elu1(acc[mf][2][2]); r1.y = elu1(acc[mf][2][3]);
        r1.z = elu1(acc[mf][3][2]); r1.w = elu1(acc[mf][3][3]);
        *reinterpret_cast<float4*>(o0)     = q0;
        *reinterpret_cast<float4*>(o0 + 4) = q1;
        *reinterpret_cast<float4*>(o1)     = r0;
        *reinterpret_cast<float4*>(o1 + 4) = r1;
    }
}

// ---------------------------------------------------------------------------
extern "C" void kernel_launch(void* const* d_in, const int* in_sizes, int n_in,
                              void* d_out, int out_size) {
    const float* x      = (const float*)d_in[0];
    const float* mu     = (const float*)d_in[1];
    const float* logstd = (const float*)d_in[2];
    const float* noise  = (const float*)d_in[3];
    float* out = (float*)d_out;

    prep<<<4096, 256>>>(x, mu, logstd, noise);

    dim3 grid(512, 8);
    conv_mma_kernel<<<grid, 256, SMEM_TOTAL>>>(out);
}

// round 17
// speedup vs baseline: 1.0852x; 1.0852x over previous
#include <cuda_runtime.h>
#include <cuda_fp16.h>
#include <cstdint>

// ---------------------------------------------------------------------------
// out[b,h,w,s,co] = ELU( conv3x3_SAME(x, W_s) ),  W_s = mu + n_s*exp(logstd)
// GEMM: C[65536,1024] = A_im2col[65536,576] * W[576,1024]; C row-major == out.
// fp16 m16n8k16 HMMA. A: CTA-resident smem halo patch + LDSM. B: weights
// pre-packed in MMA FRAGMENT ORDER (N-permuted for a coalesced epilogue).
// R16 = R14 (best) with next-step loads interleaved through the HMMA block
// (R15's L1-prefetch regressed: extra L2 sectors; reverted).
// ---------------------------------------------------------------------------
#define NS    8
#define CINV  64
#define COUTV 128
#define NTOTV 1024
#define NTAP  9
#define PSTR  72
#define PATCH_HALFS (264 * PSTR)            // 4 h-rows x 66 w
#define SMEM_TOTAL (PATCH_HALFS * 2)        // 38016 B
#define WF_TAP (128 * 4 * 32)               // uint2 elems per tap in g_Wf

__device__ __half g_Xh[16 * 64 * 64 * CINV];
// B in fragment order: [tap][n8=0..127][kk=0..3][lane=0..31] -> uint2 {b0,b1}
__device__ uint2 g_Wf[NTAP * WF_TAP];

// ============================ helpers ======================================
__device__ __forceinline__ void cp_async16(uint32_t dst, const void* src) {
    asm volatile("cp.async.cg.shared.global [%0], [%1], 16;" :: "r"(dst), "l"(src));
}
__device__ __forceinline__ void cp_commit() { asm volatile("cp.async.commit_group;"); }
template <int N> __device__ __forceinline__ void cp_wait() {
    asm volatile("cp.async.wait_group %0;" :: "n"(N));
}
__device__ __forceinline__ uint32_t smem_u32(const void* p) {
    uint32_t a;
    asm("{ .reg .u64 t; cvta.to.shared.u64 t, %1; cvt.u32.u64 %0, t; }" : "=r"(a) : "l"(p));
    return a;
}
__device__ __forceinline__ void ldsm4(uint32_t& r0, uint32_t& r1, uint32_t& r2,
                                      uint32_t& r3, uint32_t addr) {
    asm volatile("ldmatrix.sync.aligned.m8n8.x4.shared.b16 {%0,%1,%2,%3}, [%4];"
                 : "=r"(r0), "=r"(r1), "=r"(r2), "=r"(r3) : "r"(addr));
}
__device__ __forceinline__ void mma_f16(float* c, const uint32_t* a, uint2 b) {
    asm volatile(
        "mma.sync.aligned.m16n8k16.row.col.f32.f16.f16.f32 "
        "{%0,%1,%2,%3}, {%4,%5,%6,%7}, {%8,%9}, {%0,%1,%2,%3};"
        : "+f"(c[0]), "+f"(c[1]), "+f"(c[2]), "+f"(c[3])
        : "r"(a[0]), "r"(a[1]), "r"(a[2]), "r"(a[3]), "r"(b.x), "r"(b.y));
}
__device__ __forceinline__ float elu1(float v) {
    return v > 0.f ? v : (__expf(v) - 1.0f);
}

struct Frags { uint32_t a[4][4]; uint2 b[4]; };

// ============================ fused prep kernel ============================
__global__ void prep(const float* __restrict__ x,
                     const float* __restrict__ mu,
                     const float* __restrict__ logstd,
                     const float* __restrict__ noise) {
    int idx = blockIdx.x * blockDim.x + threadIdx.x;      // 1048576 threads
    float4 v = reinterpret_cast<const float4*>(x)[idx];
    __half2* xo = reinterpret_cast<__half2*>(g_Xh) + idx * 2;
    xo[0] = __floats2half2_rn(v.x, v.y);
    xo[1] = __floats2half2_rn(v.z, v.w);

    if (idx < NTAP * WF_TAP) {                            // 147456
        int lane = idx & 31;
        int kk   = (idx >> 5) & 3;
        int n8   = (idx >> 7) & 127;
        int tap  = idx >> 14;
        // N-permutation: (n8 = group*4 + nf, nj = lane>>2) -> column
        // group*32 + (nj>>1)*8 + nf*2 + (nj&1): each lane's epilogue values
        // land on 8 contiguous output columns.
        int nf   = n8 & 3;
        int nj   = lane >> 2;
        int n    = ((n8 >> 2) << 5) + ((nj >> 1) << 3) + (nf << 1) + (nj & 1);
        int s  = n >> 7, co = n & 127;
        int k0 = (kk << 4) + ((lane & 3) << 1);
        float w[4];
        #pragma unroll
        for (int j = 0; j < 4; j++) {
            int ci = k0 + (j >> 1) * 8 + (j & 1);
            int mi = (tap * CINV + ci) * COUTV + co;
            int ni = ((s * NTAP + tap) * CINV + ci) * COUTV + co;
            w[j] = mu[mi] + noise[ni] * expf(logstd[mi]);
        }
        uint2 r;
        __half2 h0 = __floats2half2_rn(w[0], w[1]);
        __half2 h1 = __floats2half2_rn(w[2], w[3]);
        r.x = *reinterpret_cast<uint32_t*>(&h0);
        r.y = *reinterpret_cast<uint32_t*>(&h1);
        g_Wf[idx] = r;
    }
}

// ============================ conv kernel ==================================
__device__ __forceinline__ void load_B_frags(Frags& F, int tap, int kk,
                                             const uint2* wf) {
    #pragma unroll
    for (int nf = 0; nf < 4; nf++)
        F.b[nf] = __ldg(wf + tap * WF_TAP + nf * 128 + kk * 32);
}
__device__ __forceinline__ void load_A_frag1(Frags& F, int tap, int kk, int mf,
                                             uint32_t pA0) {
    const int dy = tap / 3 - 1, dx = tap % 3 - 1;
    const uint32_t aBase = pA0 + (uint32_t)((dy * 66 + dx) * PSTR * 2 + kk * 32);
    ldsm4(F.a[mf][0], F.a[mf][1], F.a[mf][2], F.a[mf][3],
          aBase + (uint32_t)(mf * 16 * PSTR * 2));
}
__device__ __forceinline__ void load_A_frags(Frags& F, int tap, int kk,
                                             uint32_t pA0) {
    #pragma unroll
    for (int mf = 0; mf < 4; mf++) load_A_frag1(F, tap, kk, mf, pA0);
}

// one kk step: B(next) first, then per-mf [A(next,mf) ; 4 HMMAs(cur,mf)]
template <int TAPN, int KKN, bool HAVE_NEXT>
__device__ __forceinline__ void kk_step(Frags& cur, Frags& nxt,
                                        uint32_t pA0, const uint2* wf,
                                        float acc[4][4][4]) {
    if (HAVE_NEXT) load_B_frags(nxt, TAPN, KKN, wf);
    #pragma unroll
    for (int mf = 0; mf < 4; mf++) {
        if (HAVE_NEXT) load_A_frag1(nxt, TAPN, KKN, mf, pA0);
        #pragma unroll
        for (int nf = 0; nf < 4; nf++)
            mma_f16(acc[mf][nf], cur.a[mf], cur.b[nf]);
    }
}

__global__ __launch_bounds__(256, 2)
void conv_mma_kernel(float* __restrict__ out) {
    extern __shared__ __half smem[];
    const uint32_t patch_u32 = smem_u32(smem);

    const int tid = threadIdx.x, wid = tid >> 5, lid = tid & 31;
    const int mtile = blockIdx.x, ntile = blockIdx.y;
    const int b  = mtile >> 5;
    const int h0 = (mtile & 31) << 1;
    const int wm = wid & 1, wn = wid >> 1;     // warp tile 64m x 32n

    const uint32_t a_lane = (uint32_t)((lid & 15) * PSTR + (lid >> 4) * 8) * 2u;
    const uint32_t pA0    = patch_u32 + (uint32_t)(((wm + 1) * 66 + 1) * PSTR * 2) + a_lane;
    const uint2* wf = g_Wf + ((size_t)(ntile * 16 + wn * 4) << 7) + lid;

    // ---- prologue: load halo patch (cp.async) ----
    #pragma unroll
    for (int i = 0; i < 9; i++) {              // 2112 chunks / 256 threads
        int lin = tid + (i << 8);
        if (lin >= 2112) break;
        int row = lin >> 3, c = lin & 7;
        int hh = row / 66, ww = row % 66;
        int h = h0 - 1 + hh, w = ww - 1;
        uint32_t dst = patch_u32 + (uint32_t)(row * PSTR + (c << 3)) * 2u;
        if ((unsigned)h < 64u && (unsigned)w < 64u) {
            cp_async16(dst, g_Xh + (size_t)(((b << 6) + h) * 64 + w) * CINV + (c << 3));
        } else {
            asm volatile("st.shared.v4.b32 [%0], {%1,%1,%1,%1};" :: "r"(dst), "r"(0u) : "memory");
        }
    }
    cp_commit();

    float acc[4][4][4];
    #pragma unroll
    for (int i = 0; i < 4; i++)
        #pragma unroll
        for (int j = 0; j < 4; j++)
            #pragma unroll
            for (int k = 0; k < 4; k++) acc[i][j][k] = 0.f;

    Frags f[2];
    load_B_frags(f[0], 0, 0, wf);   // independent of the patch

    cp_wait<0>();
    __syncthreads();                // the only barrier

    load_A_frags(f[0], 0, 0, pA0);

    // Mainloop: 36 fully-unrolled kk steps with interleaved next-step loads.
    #pragma unroll
    for (int step = 0; step < 36; step++) {
        const int tap = step >> 2, kk = step & 3;
        const int ntap = (step + 1) >> 2, nkk = (step + 1) & 3;
        Frags& cur = f[step & 1];
        Frags& nxt = f[(step & 1) ^ 1];
        if (step < 35) {
            // TAPN/KKN must be compile-time: the unrolled body makes them so.
            load_B_frags(nxt, ntap, nkk, wf);
            #pragma unroll
            for (int mf = 0; mf < 4; mf++) {
                load_A_frag1(nxt, ntap, nkk, mf, pA0);
                #pragma unroll
                for (int nf = 0; nf < 4; nf++)
                    mma_f16(acc[mf][nf], cur.a[mf], cur.b[nf]);
            }
        } else {
            #pragma unroll
            for (int mf = 0; mf < 4; mf++)
                #pragma unroll
                for (int nf = 0; nf < 4; nf++)
                    mma_f16(acc[mf][nf], cur.a[mf], cur.b[nf]);
        }
    }

    // ---- epilogue: fast ELU + coalesced float4 stores ----
    const int l4 = lid >> 2, lm = lid & 3;
    const int colb = (ntile << 7) + (wn << 5) + (lm << 3);
    #pragma unroll
    for (int mf = 0; mf < 4; mf++) {
        int row = (mtile << 7) + wm * 64 + mf * 16 + l4;
        float* o0 = out + (size_t)row * NTOTV + colb;      // row l4
        float* o1 = o0 + 8 * NTOTV;                        // row l4+8
        float4 q0, q1, r0, r1;
        q0.x = elu1(acc[mf][0][0]); q0.y = elu1(acc[mf][0][1]);
        q0.z = elu1(acc[mf][1][0]); q0.w = elu1(acc[mf][1][1]);
        q1.x = elu1(acc[mf][2][0]); q1.y = elu1(acc[mf][2][1]);
        q1.z = elu1(acc[mf][3][0]); q1.w = elu1(acc[mf][3][1]);
        r0.x = elu1(acc[mf][0][2]); r0.y = elu1(acc[mf][0][3]);
        r0.z = elu1(acc[mf][1][2]); r0.w = elu1(acc[mf][1][3]);
        r1.x = elu1(acc[mf][2][2]); r1.y = elu1(acc[mf][2][3]);
        r1.z = elu1(acc[mf][3][2]); r1.w = elu1(acc[mf][3][3]);
        *reinterpret_cast<float4*>(o0)     = q0;
        *reinterpret_cast<float4*>(o0 + 4) = q1;
        *reinterpret_cast<float4*>(o1)     = r0;
        *reinterpret_cast<float4*>(o1 + 4) = r1;
    }
}

// ---------------------------------------------------------------------------
extern "C" void kernel_launch(void* const* d_in, const int* in_sizes, int n_in,
                              void* d_out, int out_size) {
    const float* x      = (const float*)d_in[0];
    const float* mu     = (const float*)d_in[1];
    const float* logstd = (const float*)d_in[2];
    const float* noise  = (const float*)d_in[3];
    float* out = (float*)d_out;

    prep<<<4096, 256>>>(x, mu, logstd, noise);

    dim3 grid(512, 8);
    conv_mma_kernel<<<grid, 256, SMEM_TOTAL>>>(out);
}